// round 2
// baseline (speedup 1.0000x reference)
#include <cuda_runtime.h>
#include <cstdint>

#define BB 4
#define DD 512
#define NN 1536
#define HH 8
#define DH 64          // per-head dim
#define NT (NN / 64)   // 24 tiles of 64

// ---------------- scratch (device globals; no allocation allowed) ----------
__device__ float g_q[(size_t)BB * HH * DH * NN];   // [b,h,d,n]
__device__ float g_k[(size_t)BB * HH * DH * NN];   // [b,h,d,n]
__device__ float g_v[(size_t)BB * HH * NN * DH];   // [b,h,m,d]
__device__ float g_s[(size_t)BB * HH * NN * NN];   // scores -> probs, [b,h,n,m]
__device__ float g_x[(size_t)BB * DD * NN];        // [b,c,n]
__device__ unsigned char g_mask[(size_t)NN * NN];  // canonical 0/1 mask
__device__ unsigned g_minenc;
__device__ unsigned g_maskflags;  // bit0: word not in {0,1}; bit1: word not in {0,0x3f800000}

// order-preserving float <-> uint encoding (unsigned compare == float compare)
__device__ __forceinline__ unsigned enc_f(float x) {
    unsigned b = __float_as_uint(x);
    return (b & 0x80000000u) ? ~b : (b | 0x80000000u);
}
__device__ __forceinline__ float dec_f(unsigned e) {
    return (e & 0x80000000u) ? __uint_as_float(e ^ 0x80000000u)
                             : __uint_as_float(~e);
}

__global__ void init_kernel() { g_minenc = 0xFFFFFFFFu; g_maskflags = 0u; }

// ---------------- mask dtype classification + normalization ----------------
// Scan the first NN*NN/4 32-bit words. NN*NN bytes is the minimum possible
// buffer size (uint8 case), so this is always in-bounds.
__global__ void __launch_bounds__(256)
mask_classify_kernel(const unsigned* __restrict__ mw) {
    const int total = NN * NN / 4;
    unsigned local = 0;
    for (int i = blockIdx.x * 256 + threadIdx.x; i < total; i += gridDim.x * 256) {
        unsigned w = mw[i];
        if (w != 0u && w != 1u)          local |= 1u;  // not plain int 0/1
        if (w != 0u && w != 0x3f800000u) local |= 2u;  // not float 0.0/1.0
    }
#pragma unroll
    for (int o = 16; o > 0; o >>= 1) local |= __shfl_xor_sync(0xffffffffu, local, o);
    if ((threadIdx.x & 31) == 0 && local) atomicOr(&g_maskflags, local);
}

__global__ void __launch_bounds__(256)
mask_convert_kernel(const void* __restrict__ mraw) {
    const unsigned f = g_maskflags;
    // mode: 2 = float32, 1 = int32, 0 = uint8
    const int mode = ((f & 2u) == 0u) ? 2 : (((f & 1u) == 0u) ? 1 : 0);
    const int total = NN * NN;
    if (mode == 0) {
        const unsigned char* m8 = (const unsigned char*)mraw;
        for (int i = blockIdx.x * 256 + threadIdx.x; i < total; i += gridDim.x * 256)
            g_mask[i] = m8[i] ? 1 : 0;
    } else if (mode == 1) {
        const int* mi = (const int*)mraw;
        for (int i = blockIdx.x * 256 + threadIdx.x; i < total; i += gridDim.x * 256)
            g_mask[i] = mi[i] ? 1 : 0;
    } else {
        const float* mf = (const float*)mraw;
        for (int i = blockIdx.x * 256 + threadIdx.x; i < total; i += gridDim.x * 256)
            g_mask[i] = (mf[i] != 0.0f) ? 1 : 0;
    }
}

// ---------------- projection: Y[b,o,n] = sum_c W[o,c] X[b,c,n] + bias[o] ----
// MODE 0: plain [b,o,n]   (final projection -> d_out)
// MODE 1: head  [b,h,d,n] (Q, K)
// MODE 2: head  [b,h,n,d] (V)
template <int MODE>
__global__ void __launch_bounds__(256)
proj_kernel(const float* __restrict__ X, const float* __restrict__ W,
            const float* __restrict__ bias, float* __restrict__ Y) {
    __shared__ float sW[64][32];  // [o][c]
    __shared__ float sX[32][64];  // [c][n]
    const int b  = blockIdx.z;
    const int o0 = blockIdx.y * 64;
    const int n0 = blockIdx.x * 64;
    const int tx = threadIdx.x, ty = threadIdx.y;
    const int t  = ty * 16 + tx;
    const float* Xb = X + (size_t)b * DD * NN;

    float acc[4][4] = {};
    for (int c0 = 0; c0 < DD; c0 += 32) {
        {   // W tile: 64 x 32
            int o = t >> 2, c = (t & 3) * 4;
            *(float4*)&sW[o][c]      = *(const float4*)&W[(size_t)(o0 + o) * DD + c0 + c];
            *(float4*)&sW[o][c + 16] = *(const float4*)&W[(size_t)(o0 + o) * DD + c0 + c + 16];
        }
        {   // X tile: 32 x 64
            int c = t >> 3, n = (t & 7) * 4;
            *(float4*)&sX[c][n]      = *(const float4*)&Xb[(size_t)(c0 + c) * NN + n0 + n];
            *(float4*)&sX[c][n + 32] = *(const float4*)&Xb[(size_t)(c0 + c) * NN + n0 + n + 32];
        }
        __syncthreads();
#pragma unroll 16
        for (int k = 0; k < 32; k++) {
            float a0 = sW[ty * 4 + 0][k];
            float a1 = sW[ty * 4 + 1][k];
            float a2 = sW[ty * 4 + 2][k];
            float a3 = sW[ty * 4 + 3][k];
            float4 bx = *(const float4*)&sX[k][tx * 4];
            acc[0][0] += a0 * bx.x; acc[0][1] += a0 * bx.y; acc[0][2] += a0 * bx.z; acc[0][3] += a0 * bx.w;
            acc[1][0] += a1 * bx.x; acc[1][1] += a1 * bx.y; acc[1][2] += a1 * bx.z; acc[1][3] += a1 * bx.w;
            acc[2][0] += a2 * bx.x; acc[2][1] += a2 * bx.y; acc[2][2] += a2 * bx.z; acc[2][3] += a2 * bx.w;
            acc[3][0] += a3 * bx.x; acc[3][1] += a3 * bx.y; acc[3][2] += a3 * bx.z; acc[3][3] += a3 * bx.w;
        }
        __syncthreads();
    }

#pragma unroll
    for (int i = 0; i < 4; i++) {
        int o  = o0 + ty * 4 + i;
        float bo = bias[o];
        float4 r = make_float4(acc[i][0] + bo, acc[i][1] + bo,
                               acc[i][2] + bo, acc[i][3] + bo);
        if (MODE == 0) {
            *(float4*)&Y[((size_t)b * DD + o) * NN + n0 + tx * 4] = r;
        } else if (MODE == 1) {
            int h = o & 7, dd = o >> 3;
            *(float4*)&Y[(((size_t)b * HH + h) * DH + dd) * NN + n0 + tx * 4] = r;
        } else {
            int h = o & 7, dd = o >> 3;
            int n = n0 + tx * 4;
            Y[(((size_t)b * HH + h) * NN + n + 0) * DH + dd] = r.x;
            Y[(((size_t)b * HH + h) * NN + n + 1) * DH + dd] = r.y;
            Y[(((size_t)b * HH + h) * NN + n + 2) * DH + dd] = r.z;
            Y[(((size_t)b * HH + h) * NN + n + 3) * DH + dd] = r.w;
        }
    }
}

// ---------------- scores: S[bh,n,m] = (1/8) sum_d Q[bh,d,n] K[bh,d,m] -------
// epilogue: global min via atomicMin on encoded uint
__global__ void __launch_bounds__(256)
scores_kernel() {
    __shared__ float sQ[64][64];  // [d][n]
    __shared__ float sK[64][64];  // [d][m]
    __shared__ float sred[8];
    const int bh = blockIdx.z;
    const int n0 = blockIdx.y * 64;
    const int m0 = blockIdx.x * 64;
    const int tx = threadIdx.x, ty = threadIdx.y;
    const int t  = ty * 16 + tx;
    const float* Q = g_q + (size_t)bh * DH * NN;
    const float* K = g_k + (size_t)bh * DH * NN;

#pragma unroll
    for (int r = 0; r < 4; r++) {
        int d = (t >> 4) + r * 16;
        int n = (t & 15) * 4;
        *(float4*)&sQ[d][n] = *(const float4*)&Q[(size_t)d * NN + n0 + n];
        *(float4*)&sK[d][n] = *(const float4*)&K[(size_t)d * NN + m0 + n];
    }
    __syncthreads();

    float acc[4][4] = {};
#pragma unroll 16
    for (int k = 0; k < 64; k++) {
        float4 a = *(const float4*)&sQ[k][ty * 4];
        float4 b = *(const float4*)&sK[k][tx * 4];
        acc[0][0] += a.x * b.x; acc[0][1] += a.x * b.y; acc[0][2] += a.x * b.z; acc[0][3] += a.x * b.w;
        acc[1][0] += a.y * b.x; acc[1][1] += a.y * b.y; acc[1][2] += a.y * b.z; acc[1][3] += a.y * b.w;
        acc[2][0] += a.z * b.x; acc[2][1] += a.z * b.y; acc[2][2] += a.z * b.z; acc[2][3] += a.z * b.w;
        acc[3][0] += a.w * b.x; acc[3][1] += a.w * b.y; acc[3][2] += a.w * b.z; acc[3][3] += a.w * b.w;
    }

    float mn = __int_as_float(0x7f800000);  // +inf
#pragma unroll
    for (int i = 0; i < 4; i++) {
        int n = n0 + ty * 4 + i;
        float4 r = make_float4(acc[i][0] * 0.125f, acc[i][1] * 0.125f,
                               acc[i][2] * 0.125f, acc[i][3] * 0.125f);
        mn = fminf(mn, fminf(fminf(r.x, r.y), fminf(r.z, r.w)));
        *(float4*)&g_s[((size_t)bh * NN + n) * NN + m0 + tx * 4] = r;
    }
    // block min -> atomic
#pragma unroll
    for (int o = 16; o > 0; o >>= 1) mn = fminf(mn, __shfl_xor_sync(0xffffffffu, mn, o));
    if ((t & 31) == 0) sred[t >> 5] = mn;
    __syncthreads();
    if (t == 0) {
        float v = sred[0];
#pragma unroll
        for (int i = 1; i < 8; i++) v = fminf(v, sred[i]);
        atomicMin(&g_minenc, enc_f(v));
    }
}

// ---------------- output 2: mean over heads of masked scores ----------------
__global__ void __launch_bounds__(256)
out2_kernel(float* __restrict__ O2) {
    const int idx = blockIdx.x * 256 + threadIdx.x;          // float4 index
    const int total = BB * NN * NN / 4;
    if (idx >= total) return;
    const int e = idx * 4;
    const int m = e % NN;
    const int n = (e / NN) % NN;
    const int b = e / (NN * NN);

    float4 acc = make_float4(0.f, 0.f, 0.f, 0.f);
#pragma unroll
    for (int h = 0; h < HH; h++) {
        float4 s = *(const float4*)&g_s[((size_t)(b * HH + h) * NN + n) * NN + m];
        acc.x += s.x; acc.y += s.y; acc.z += s.z; acc.w += s.w;
    }
    const float pen = dec_f(g_minenc) - 20.0f;
    uchar4 mk = *(const uchar4*)&g_mask[(size_t)n * NN + m];
    acc.x = acc.x * 0.125f + (mk.x ? 0.f : pen);
    acc.y = acc.y * 0.125f + (mk.y ? 0.f : pen);
    acc.z = acc.z * 0.125f + (mk.z ? 0.f : pen);
    acc.w = acc.w * 0.125f + (mk.w ? 0.f : pen);
    *(float4*)&O2[e] = acc;
}

// ---------------- softmax (in place, scores -> probs) -----------------------
__global__ void __launch_bounds__(256)
softmax_kernel() {
    const int row = blockIdx.x;               // bh*NN + n
    const int n   = row % NN;
    float* S = g_s + (size_t)row * NN;
    const unsigned char* mrow = g_mask + (size_t)n * NN;
    const int tid = threadIdx.x;
    const float pen = dec_f(g_minenc) - 20.0f;

    __shared__ float sredA[8];
    __shared__ float sredB[8];

    float v[6];
    float mx = __int_as_float(0xff800000);  // -inf
#pragma unroll
    for (int i = 0; i < 6; i++) {
        int m = tid + i * 256;
        float s = S[m];
        if (!mrow[m]) s += pen;
        v[i] = s;
        mx = fmaxf(mx, s);
    }
#pragma unroll
    for (int o = 16; o > 0; o >>= 1) mx = fmaxf(mx, __shfl_xor_sync(0xffffffffu, mx, o));
    if ((tid & 31) == 0) sredA[tid >> 5] = mx;
    __syncthreads();
    mx = sredA[0];
#pragma unroll
    for (int i = 1; i < 8; i++) mx = fmaxf(mx, sredA[i]);

    float sum = 0.f;
#pragma unroll
    for (int i = 0; i < 6; i++) {
        v[i] = __expf(v[i] - mx);
        sum += v[i];
    }
#pragma unroll
    for (int o = 16; o > 0; o >>= 1) sum += __shfl_xor_sync(0xffffffffu, sum, o);
    if ((tid & 31) == 0) sredB[tid >> 5] = sum;
    __syncthreads();
    sum = sredB[0];
#pragma unroll
    for (int i = 1; i < 8; i++) sum += sredB[i];
    const float inv = 1.0f / sum;
#pragma unroll
    for (int i = 0; i < 6; i++) S[tid + i * 256] = v[i] * inv;
}

// ---------------- PV: X[n,d] = sum_m P[n,m] V[m,d]  -> g_x[b, d*8+h, n] -----
__global__ void __launch_bounds__(256)
pv_kernel() {
    __shared__ float sP[64][64];  // [n][m]
    __shared__ float sV[64][64];  // [m][d]
    const int bh = blockIdx.y;
    const int n0 = blockIdx.x * 64;
    const int tx = threadIdx.x, ty = threadIdx.y;
    const int t  = ty * 16 + tx;
    const float* P = g_s + (size_t)bh * NN * NN;
    const float* V = g_v + (size_t)bh * NN * DH;

    float acc[4][4] = {};
    for (int m0 = 0; m0 < NN; m0 += 64) {
#pragma unroll
        for (int r = 0; r < 4; r++) {
            int rr = (t >> 4) + r * 16;
            int c  = (t & 15) * 4;
            *(float4*)&sP[rr][c] = *(const float4*)&P[(size_t)(n0 + rr) * NN + m0 + c];
            *(float4*)&sV[rr][c] = *(const float4*)&V[(size_t)(m0 + rr) * DH + c];
        }
        __syncthreads();
#pragma unroll 16
        for (int k = 0; k < 64; k++) {
            float a0 = sP[ty * 4 + 0][k];
            float a1 = sP[ty * 4 + 1][k];
            float a2 = sP[ty * 4 + 2][k];
            float a3 = sP[ty * 4 + 3][k];
            float4 b = *(const float4*)&sV[k][tx * 4];
            acc[0][0] += a0 * b.x; acc[0][1] += a0 * b.y; acc[0][2] += a0 * b.z; acc[0][3] += a0 * b.w;
            acc[1][0] += a1 * b.x; acc[1][1] += a1 * b.y; acc[1][2] += a1 * b.z; acc[1][3] += a1 * b.w;
            acc[2][0] += a2 * b.x; acc[2][1] += a2 * b.y; acc[2][2] += a2 * b.z; acc[2][3] += a2 * b.w;
            acc[3][0] += a3 * b.x; acc[3][1] += a3 * b.y; acc[3][2] += a3 * b.z; acc[3][3] += a3 * b.w;
        }
        __syncthreads();
    }

    const int b = bh >> 3, h = bh & 7;
#pragma unroll
    for (int j = 0; j < 4; j++) {
        int d = tx * 4 + j;
        int c = d * 8 + h;
        float4 r = make_float4(acc[0][j], acc[1][j], acc[2][j], acc[3][j]);
        *(float4*)&g_x[((size_t)b * DD + c) * NN + n0 + ty * 4] = r;
    }
}

// ---------------- launch ----------------------------------------------------
extern "C" void kernel_launch(void* const* d_in, const int* in_sizes, int n_in,
                              void* d_out, int out_size) {
    const float* query = (const float*)d_in[0];
    const float* key   = (const float*)d_in[1];
    const float* value = (const float*)d_in[2];
    // d_in[3] = dist (unused)
    const void* mask   = d_in[4];
    const float* Wq = (const float*)d_in[5];
    const float* bq = (const float*)d_in[6];
    const float* Wk = (const float*)d_in[7];
    const float* bk = (const float*)d_in[8];
    const float* Wv = (const float*)d_in[9];
    const float* bv = (const float*)d_in[10];
    const float* Wm = (const float*)d_in[11];
    const float* bm = (const float*)d_in[12];

    float* out  = (float*)d_out;                         // [B, D, N]
    float* out2 = out + (size_t)BB * DD * NN;            // [B, N, N]

    float *pq, *pk, *pv, *px;
    cudaGetSymbolAddress((void**)&pq, g_q);
    cudaGetSymbolAddress((void**)&pk, g_k);
    cudaGetSymbolAddress((void**)&pv, g_v);
    cudaGetSymbolAddress((void**)&px, g_x);

    init_kernel<<<1, 1>>>();

    mask_classify_kernel<<<256, 256>>>((const unsigned*)mask);
    mask_convert_kernel<<<256, 256>>>(mask);

    dim3 tb(16, 16);
    dim3 gproj(NT, DD / 64, BB);
    proj_kernel<1><<<gproj, tb>>>(query, Wq, bq, pq);
    proj_kernel<1><<<gproj, tb>>>(key,   Wk, bk, pk);
    proj_kernel<2><<<gproj, tb>>>(value, Wv, bv, pv);

    scores_kernel<<<dim3(NT, NT, BB * HH), tb>>>();

    {
        int total4 = BB * NN * NN / 4;
        out2_kernel<<<(total4 + 255) / 256, 256>>>(out2);
    }

    softmax_kernel<<<BB * HH * NN, 256>>>();

    pv_kernel<<<dim3(NT, BB * HH), tb>>>();

    proj_kernel<0><<<gproj, tb>>>(px, Wm, bm, out);
}